// round 1
// baseline (speedup 1.0000x reference)
#include <cuda_runtime.h>

#define N_NODES 2048
#define NODE_DIM 128
#define HIDDEN 64

// Scratch (no allocation allowed — device globals)
__device__ __align__(16) float g_Wc[NODE_DIM * 2 * HIDDEN];   // [128][128] combined enc->a|b weights
__device__ __align__(16) float g_bc[2 * HIDDEN];              // combined biases (b1 folded into A half)
__device__ __align__(16) float g_AB[N_NODES * 2 * HIDDEN];    // [2048][128]: cols 0..63 = a_i (+bias), 64..127 = b_i

// ---------------------------------------------------------------------------
// P1: combine weights.  Wc[d][h'] = sum_k W_enc[d][k] * W1[sel(k,h')][h]
//     bc[h']            = sum_k b_enc[k] * W1[...] (+ b1 for A half)
// ---------------------------------------------------------------------------
__global__ void prep_weights(const float* __restrict__ W_enc,
                             const float* __restrict__ b_enc,
                             const float* __restrict__ W1,
                             const float* __restrict__ b1)
{
    if (blockIdx.x < 64) {
        int out = blockIdx.x * 256 + threadIdx.x;       // 0..16383
        int d  = out >> 7;
        int hp = out & 127;
        int h    = (hp < HIDDEN) ? hp : hp - HIDDEN;
        int koff = (hp < HIDDEN) ? 0  : HIDDEN;
        float acc = 0.f;
        #pragma unroll 8
        for (int k = 0; k < HIDDEN; k++)
            acc += W_enc[d * HIDDEN + k] * W1[(koff + k) * HIDDEN + h];
        g_Wc[d * 128 + hp] = acc;
    } else {
        int hp = threadIdx.x;
        if (hp < 128) {
            int h    = (hp < HIDDEN) ? hp : hp - HIDDEN;
            int koff = (hp < HIDDEN) ? 0  : HIDDEN;
            float acc = (hp < HIDDEN) ? b1[hp] : 0.f;
            #pragma unroll 8
            for (int k = 0; k < HIDDEN; k++)
                acc += b_enc[k] * W1[(koff + k) * HIDDEN + h];
            g_bc[hp] = acc;
        }
    }
}

// ---------------------------------------------------------------------------
// P2: AB = X @ Wc + bc     (2048 x 128 x 128 GEMM, f32x2 packed over h)
// grid 256 blocks: bid>>1 = 16-row tile, bid&1 = column half (A or B)
// ---------------------------------------------------------------------------
__global__ __launch_bounds__(256, 2) void prep_AB(const float* __restrict__ X)
{
    __shared__ float Xs[16][NODE_DIM];                      // 8 KB
    __shared__ unsigned long long Ws2[NODE_DIM][32];        // 32 KB (this half's 64 cols as pairs)

    const int t    = threadIdx.x;
    const int half = blockIdx.x & 1;
    const int r0   = (blockIdx.x >> 1) * 16;

    for (int idx = t; idx < NODE_DIM * 32; idx += 256) {
        int d = idx >> 5, p = idx & 31;
        Ws2[d][p] = *(const unsigned long long*)&g_Wc[d * 128 + half * HIDDEN + 2 * p];
    }
    for (int idx = t; idx < 16 * NODE_DIM; idx += 256) {
        int r = idx >> 7, d = idx & 127;
        Xs[r][d] = X[(r0 + r) * NODE_DIM + d];
    }
    __syncthreads();

    const int tx = t & 15;      // column-pair base
    const int ty = t >> 4;      // row
    unsigned long long acc0 = 0ull, acc1 = 0ull;

    #pragma unroll 4
    for (int d = 0; d < NODE_DIM; d++) {
        unsigned xu = __float_as_uint(Xs[ty][d]);
        unsigned long long x2;
        asm("mov.b64 %0, {%1, %2};" : "=l"(x2) : "r"(xu), "r"(xu));
        unsigned long long w0 = Ws2[d][tx];
        unsigned long long w1 = Ws2[d][tx + 16];
        asm("fma.rn.f32x2 %0, %1, %2, %0;" : "+l"(acc0) : "l"(x2), "l"(w0));
        asm("fma.rn.f32x2 %0, %1, %2, %0;" : "+l"(acc1) : "l"(x2), "l"(w1));
    }

    const int row = r0 + ty;
    #pragma unroll
    for (int u = 0; u < 2; u++) {
        unsigned long long a = u ? acc1 : acc0;
        unsigned lo_u, hi_u;
        asm("mov.b64 {%0, %1}, %2;" : "=r"(lo_u), "=r"(hi_u) : "l"(a));
        int hp = half * HIDDEN + 2 * (tx + 16 * u);
        float2 v;
        v.x = __uint_as_float(lo_u) + g_bc[hp];
        v.y = __uint_as_float(hi_u) + g_bc[hp + 1];
        *(float2*)&g_AB[row * 128 + hp] = v;
    }
}

// ---------------------------------------------------------------------------
// Main: out[i][j] = sigmoid( sum_h relu(A[i][h]+B[j][h]) * W2[h] + b2 ), diag=0
// 64x64 tile per block, 256 threads, 4x4 micro-tile, f32x2 packed over h.
// Smem tiles XOR-swizzled: col index (hh ^ (row&31)) -> conflict-free LDS.64.
// ---------------------------------------------------------------------------
__global__ __launch_bounds__(256, 2) void pairwise(const float* __restrict__ W2,
                                                   const float* __restrict__ b2p,
                                                   float* __restrict__ out)
{
    __shared__ unsigned long long As2[64 * 32];   // 16 KB
    __shared__ unsigned long long Bs2[64 * 32];   // 16 KB
    __shared__ unsigned long long w2s[32];

    const int t  = threadIdx.x;
    const int i0 = blockIdx.y * 64;
    const int j0 = blockIdx.x * 64;

    for (int idx = t; idx < 64 * 32; idx += 256) {
        int r = idx >> 5, hh = idx & 31;
        int sc = hh ^ (r & 31);
        As2[r * 32 + sc] = *(const unsigned long long*)&g_AB[(i0 + r) * 128 + 2 * hh];
        Bs2[r * 32 + sc] = *(const unsigned long long*)&g_AB[(j0 + r) * 128 + HIDDEN + 2 * hh];
    }
    if (t < 32) w2s[t] = *(const unsigned long long*)&W2[2 * t];
    __syncthreads();

    const int tx = t & 15;      // j = j0 + tx + 16c
    const int ty = t >> 4;      // i = i0 + ty + 16r

    unsigned long long acc[4][4];
    #pragma unroll
    for (int r = 0; r < 4; r++)
        #pragma unroll
        for (int c = 0; c < 4; c++) acc[r][c] = 0ull;

    #pragma unroll 8
    for (int hh = 0; hh < 32; hh++) {
        const unsigned long long w2 = w2s[hh];
        unsigned long long av[4], bv[4];
        #pragma unroll
        for (int r = 0; r < 4; r++) {
            int i = ty + 16 * r;
            av[r] = As2[i * 32 + (hh ^ (i & 31))];
        }
        #pragma unroll
        for (int c = 0; c < 4; c++) {
            int j = tx + 16 * c;
            bv[c] = Bs2[j * 32 + (hh ^ (j & 31))];
        }
        #pragma unroll
        for (int r = 0; r < 4; r++) {
            #pragma unroll
            for (int c = 0; c < 4; c++) {
                unsigned long long s;
                asm("add.rn.f32x2 %0, %1, %2;" : "=l"(s) : "l"(av[r]), "l"(bv[c]));
                unsigned lo_u, hi_u;
                asm("mov.b64 {%0, %1}, %2;" : "=r"(lo_u), "=r"(hi_u) : "l"(s));
                float lo = fmaxf(__uint_as_float(lo_u), 0.0f);
                float hi = fmaxf(__uint_as_float(hi_u), 0.0f);
                asm("mov.b64 %0, {%1, %2};" : "=l"(s)
                    : "r"(__float_as_uint(lo)), "r"(__float_as_uint(hi)));
                asm("fma.rn.f32x2 %0, %1, %2, %0;" : "+l"(acc[r][c]) : "l"(s), "l"(w2));
            }
        }
    }

    const float bias2 = __ldg(b2p);
    #pragma unroll
    for (int r = 0; r < 4; r++) {
        const int i = i0 + ty + 16 * r;
        #pragma unroll
        for (int c = 0; c < 4; c++) {
            const int j = j0 + tx + 16 * c;
            unsigned lo_u, hi_u;
            asm("mov.b64 {%0, %1}, %2;" : "=r"(lo_u), "=r"(hi_u) : "l"(acc[r][c]));
            float logit = __uint_as_float(lo_u) + __uint_as_float(hi_u) + bias2;
            float T = 1.0f / (1.0f + __expf(-logit));
            out[i * N_NODES + j] = (i == j) ? 0.0f : T;
        }
    }
}

extern "C" void kernel_launch(void* const* d_in, const int* in_sizes, int n_in,
                              void* d_out, int out_size)
{
    const float* X     = (const float*)d_in[0];
    const float* W_enc = (const float*)d_in[1];
    const float* b_enc = (const float*)d_in[2];
    const float* W1    = (const float*)d_in[3];
    const float* b1    = (const float*)d_in[4];
    const float* W2    = (const float*)d_in[5];
    const float* b2    = (const float*)d_in[6];
    float* out = (float*)d_out;

    prep_weights<<<65, 256>>>(W_enc, b_enc, W1, b1);
    prep_AB<<<256, 256>>>(X);
    dim3 grid(N_NODES / 64, N_NODES / 64);
    pairwise<<<grid, 256>>>(W2, b2, out);
}